// round 1
// baseline (speedup 1.0000x reference)
#include <cuda_runtime.h>
#include <cstdint>

// Problem constants
#define Bsz  4
#define Nseq 2048
#define Cdim 768
#define Hn   12
#define Dh   64
#define Mrows (Bsz * Nseq)   // 8192
#define SCALE_F 0.125f       // 64^-0.5

// Scratch (device globals: allocation-free rule)
__device__ float g_q[Mrows * Cdim];   // [B,H,N,D]
__device__ float g_k[Mrows * Cdim];   // [B,H,N,D]
__device__ float g_v[Mrows * Cdim];   // [B,H,N,D]
__device__ float g_o[Mrows * Cdim];   // [B,N,C]
__device__ float g_uc[Mrows];         // [B,N]

// ---------------------------------------------------------------------------
// SGEMM: Y[M,Nc] = A[M,K] @ W^T  (W stored [Nc,K] row-major), M=8192, Nc=K=768
// BM=BN=128, BK=16, 256 threads, 8x8 per thread.
// HEAD_REMAP: write Y as [B,H,N,D] instead of [M,Nc].
// ---------------------------------------------------------------------------
template<int HEAD_REMAP, int HAS_BIAS>
__global__ __launch_bounds__(256, 2) void sgemm_kernel(
    const float* __restrict__ A, const float* __restrict__ W,
    const float* __restrict__ bias, float* __restrict__ Y)
{
    const int BM = 128, BN = 128, BK = 16;
    __shared__ float As[BK][BM + 4];
    __shared__ float Bs[BK][BN + 4];

    int t  = threadIdx.x;
    int tx = t & 15;      // column group (8 cols)
    int ty = t >> 4;      // row group    (8 rows)
    int m0 = blockIdx.y * BM;
    int n0 = blockIdx.x * BN;

    float acc[8][8];
#pragma unroll
    for (int i = 0; i < 8; i++)
#pragma unroll
        for (int j = 0; j < 8; j++) acc[i][j] = 0.0f;

    // Load mapping: each thread brings 8 floats (2x float4) of A and W per k-step
    int la_m = t >> 1;            // 0..127
    int la_k = (t & 1) * 8;       // 0 or 8
    const float* Aptr = A + (size_t)(m0 + la_m) * Cdim + la_k;
    const float* Wptr = W + (size_t)(n0 + la_m) * Cdim + la_k;

    for (int kb = 0; kb < Cdim; kb += BK) {
        float4 a0 = *(const float4*)(Aptr + kb);
        float4 a1 = *(const float4*)(Aptr + kb + 4);
        float4 b0 = *(const float4*)(Wptr + kb);
        float4 b1 = *(const float4*)(Wptr + kb + 4);

        __syncthreads();  // previous tile fully consumed
        As[la_k + 0][la_m] = a0.x;  As[la_k + 1][la_m] = a0.y;
        As[la_k + 2][la_m] = a0.z;  As[la_k + 3][la_m] = a0.w;
        As[la_k + 4][la_m] = a1.x;  As[la_k + 5][la_m] = a1.y;
        As[la_k + 6][la_m] = a1.z;  As[la_k + 7][la_m] = a1.w;
        Bs[la_k + 0][la_m] = b0.x;  Bs[la_k + 1][la_m] = b0.y;
        Bs[la_k + 2][la_m] = b0.z;  Bs[la_k + 3][la_m] = b0.w;
        Bs[la_k + 4][la_m] = b1.x;  Bs[la_k + 5][la_m] = b1.y;
        Bs[la_k + 6][la_m] = b1.z;  Bs[la_k + 7][la_m] = b1.w;
        __syncthreads();

#pragma unroll
        for (int kk = 0; kk < BK; kk++) {
            float ar[8], br[8];
            *(float4*)(ar)     = *(const float4*)&As[kk][ty * 8];
            *(float4*)(ar + 4) = *(const float4*)&As[kk][ty * 8 + 4];
            *(float4*)(br)     = *(const float4*)&Bs[kk][tx * 8];
            *(float4*)(br + 4) = *(const float4*)&Bs[kk][tx * 8 + 4];
#pragma unroll
            for (int i = 0; i < 8; i++)
#pragma unroll
                for (int j = 0; j < 8; j++)
                    acc[i][j] = fmaf(ar[i], br[j], acc[i][j]);
        }
    }

    // Epilogue
#pragma unroll
    for (int i = 0; i < 8; i++) {
        int mg = m0 + ty * 8 + i;
#pragma unroll
        for (int jj = 0; jj < 8; jj += 4) {
            int ng = n0 + tx * 8 + jj;
            float4 r4 = make_float4(acc[i][jj], acc[i][jj + 1], acc[i][jj + 2], acc[i][jj + 3]);
            if (HEAD_REMAP) {
                int b = mg >> 11;          // / Nseq
                int n = mg & (Nseq - 1);
                int h = ng >> 6;           // / Dh (8-aligned ng never crosses head)
                int d = ng & (Dh - 1);
                size_t idx = (((size_t)(b * Hn + h) * Nseq + n) << 6) + d;
                *(float4*)&Y[idx] = r4;
            } else {
                if (HAS_BIAS) {
                    float4 bb = *(const float4*)&bias[ng];
                    r4.x += bb.x; r4.y += bb.y; r4.z += bb.z; r4.w += bb.w;
                }
                *(float4*)&Y[(size_t)mg * Cdim + ng] = r4;
            }
        }
    }
}

// ---------------------------------------------------------------------------
// uc[row] = mean over C of x_u[row, :]   (one warp per row)
// ---------------------------------------------------------------------------
__global__ void uc_kernel(const float* __restrict__ xu, float* __restrict__ uc)
{
    int warp = (blockIdx.x * blockDim.x + threadIdx.x) >> 5;
    int lane = threadIdx.x & 31;
    if (warp >= Mrows) return;
    const float* row = xu + (size_t)warp * Cdim;
    float s = 0.0f;
#pragma unroll
    for (int i = 0; i < Cdim / 32; i++) s += row[lane + i * 32];
#pragma unroll
    for (int m = 16; m; m >>= 1) s += __shfl_xor_sync(0xffffffffu, s, m);
    if (lane == 0) uc[warp] = s * (1.0f / Cdim);
}

// ---------------------------------------------------------------------------
// Fused attention: per (b,h), 64-query tile, stream 64-key tiles,
// online softmax. S includes SCALE * uc[q] folded into Q rows.
// smem: Qt[d][r], KP (Kt[d][n] then Ps[r][c]), Vs[n][d] = 48 KB
// 256 threads: thread (ty,tx) owns 4x4 of the 64x64 S / O tiles.
// ---------------------------------------------------------------------------
__global__ __launch_bounds__(256, 2) void attn_kernel(
    const float* __restrict__ Q, const float* __restrict__ K,
    const float* __restrict__ V, const float* __restrict__ UC,
    float* __restrict__ O)
{
    __shared__ float Qt[64][64];   // Qt[d][r]  (transposed, pre-scaled)
    __shared__ float KP[64][64];   // Kt[d][n] during S;  Ps[r][c] during PV
    __shared__ float Vs[64][64];   // Vs[n][d]

    int t  = threadIdx.x;
    int tx = t & 15;
    int ty = t >> 4;
    int bh = blockIdx.y;
    int b  = bh / Hn;
    int h  = bh - b * Hn;
    int q0 = blockIdx.x * 64;

    const float* Qb = Q + ((size_t)bh * Nseq + q0) * Dh;
    const float* Kb = K + (size_t)bh * Nseq * Dh;
    const float* Vb = V + (size_t)bh * Nseq * Dh;

    // Stage Q (transposed) with SCALE*uc folded in
    {
        int r  = t >> 2;
        int d0 = (t & 3) * 16;
        float sc = UC[b * Nseq + q0 + r] * SCALE_F;
#pragma unroll
        for (int i = 0; i < 16; i += 4) {
            float4 v4 = *(const float4*)(Qb + (size_t)r * Dh + d0 + i);
            Qt[d0 + i + 0][r] = v4.x * sc;
            Qt[d0 + i + 1][r] = v4.y * sc;
            Qt[d0 + i + 2][r] = v4.z * sc;
            Qt[d0 + i + 3][r] = v4.w * sc;
        }
    }

    float m_i[4], l_i[4], o[4][4];
#pragma unroll
    for (int i = 0; i < 4; i++) {
        m_i[i] = -1e30f; l_i[i] = 0.0f;
#pragma unroll
        for (int j = 0; j < 4; j++) o[i][j] = 0.0f;
    }

    int lr  = t >> 2;          // load row 0..63
    int ld0 = (t & 3) * 16;    // load col group

    for (int kt = 0; kt < Nseq; kt += 64) {
        __syncthreads();   // prior tile fully consumed (also covers Qt stage, iter 0)

        // Load K (transposed) and V
#pragma unroll
        for (int i = 0; i < 16; i += 4) {
            float4 kv = *(const float4*)(Kb + (size_t)(kt + lr) * Dh + ld0 + i);
            KP[ld0 + i + 0][lr] = kv.x;
            KP[ld0 + i + 1][lr] = kv.y;
            KP[ld0 + i + 2][lr] = kv.z;
            KP[ld0 + i + 3][lr] = kv.w;
            *(float4*)&Vs[lr][ld0 + i] =
                *(const float4*)(Vb + (size_t)(kt + lr) * Dh + ld0 + i);
        }
        __syncthreads();

        // S = Qs * K^T  (64x64, 4x4 per thread)
        float acc[4][4];
#pragma unroll
        for (int i = 0; i < 4; i++)
#pragma unroll
            for (int j = 0; j < 4; j++) acc[i][j] = 0.0f;
#pragma unroll 16
        for (int d = 0; d < 64; d++) {
            float a[4], bb[4];
            *(float4*)a  = *(const float4*)&Qt[d][ty * 4];
            *(float4*)bb = *(const float4*)&KP[d][tx * 4];
#pragma unroll
            for (int i = 0; i < 4; i++)
#pragma unroll
                for (int j = 0; j < 4; j++)
                    acc[i][j] = fmaf(a[i], bb[j], acc[i][j]);
        }

        // Online softmax (row stats across 16 lanes sharing ty)
#pragma unroll
        for (int i = 0; i < 4; i++) {
            float tm = fmaxf(fmaxf(acc[i][0], acc[i][1]), fmaxf(acc[i][2], acc[i][3]));
#pragma unroll
            for (int msk = 8; msk; msk >>= 1)
                tm = fmaxf(tm, __shfl_xor_sync(0xffffffffu, tm, msk));
            float m_new = fmaxf(m_i[i], tm);
            float corr  = __expf(m_i[i] - m_new);
            m_i[i] = m_new;
            float rs = 0.0f;
#pragma unroll
            for (int j = 0; j < 4; j++) {
                acc[i][j] = __expf(acc[i][j] - m_new);
                rs += acc[i][j];
            }
#pragma unroll
            for (int msk = 8; msk; msk >>= 1)
                rs += __shfl_xor_sync(0xffffffffu, rs, msk);
            l_i[i] = l_i[i] * corr + rs;
#pragma unroll
            for (int j = 0; j < 4; j++) o[i][j] *= corr;
        }

        __syncthreads();   // everyone done reading KP as K
        // Write P into KP (Ps[r][c])
#pragma unroll
        for (int i = 0; i < 4; i++)
            *(float4*)&KP[ty * 4 + i][tx * 4] =
                make_float4(acc[i][0], acc[i][1], acc[i][2], acc[i][3]);
        __syncthreads();

        // O += P * V
#pragma unroll 16
        for (int k = 0; k < 64; k++) {
            float bb[4];
            *(float4*)bb = *(const float4*)&Vs[k][tx * 4];
            float a0 = KP[ty * 4 + 0][k];
            float a1 = KP[ty * 4 + 1][k];
            float a2 = KP[ty * 4 + 2][k];
            float a3 = KP[ty * 4 + 3][k];
#pragma unroll
            for (int j = 0; j < 4; j++) {
                o[0][j] = fmaf(a0, bb[j], o[0][j]);
                o[1][j] = fmaf(a1, bb[j], o[1][j]);
                o[2][j] = fmaf(a2, bb[j], o[2][j]);
                o[3][j] = fmaf(a3, bb[j], o[3][j]);
            }
        }
    }

    // Epilogue: normalize, write [B,N,C]
#pragma unroll
    for (int i = 0; i < 4; i++) {
        float inv = 1.0f / l_i[i];
        int q = q0 + ty * 4 + i;
        float4 r4 = make_float4(o[i][0] * inv, o[i][1] * inv, o[i][2] * inv, o[i][3] * inv);
        *(float4*)&O[(size_t)(b * Nseq + q) * Cdim + h * Dh + tx * 4] = r4;
    }
}

// ---------------------------------------------------------------------------
extern "C" void kernel_launch(void* const* d_in, const int* in_sizes, int n_in,
                              void* d_out, int out_size)
{
    const float* x_q = (const float*)d_in[0];
    const float* x_k = (const float*)d_in[1];
    const float* x_v = (const float*)d_in[2];
    const float* x_u = (const float*)d_in[3];
    const float* Wq  = (const float*)d_in[4];
    const float* Wk  = (const float*)d_in[5];
    const float* Wv  = (const float*)d_in[6];
    const float* Wp  = (const float*)d_in[7];
    const float* bp  = (const float*)d_in[8];
    float* out = (float*)d_out;

    float *gq, *gk, *gv, *go, *guc;
    cudaGetSymbolAddress((void**)&gq,  g_q);
    cudaGetSymbolAddress((void**)&gk,  g_k);
    cudaGetSymbolAddress((void**)&gv,  g_v);
    cudaGetSymbolAddress((void**)&go,  g_o);
    cudaGetSymbolAddress((void**)&guc, g_uc);

    dim3 gemm_grid(Cdim / 128, Mrows / 128);   // (6, 64)
    sgemm_kernel<1, 0><<<gemm_grid, 256>>>(x_q, Wq, nullptr, gq);
    sgemm_kernel<1, 0><<<gemm_grid, 256>>>(x_k, Wk, nullptr, gk);
    sgemm_kernel<1, 0><<<gemm_grid, 256>>>(x_v, Wv, nullptr, gv);

    uc_kernel<<<Mrows / 8, 256>>>(x_u, guc);

    dim3 attn_grid(Nseq / 64, Bsz * Hn);       // (32, 48)
    attn_kernel<<<attn_grid, 256>>>(gq, gk, gv, guc, go);

    sgemm_kernel<0, 1><<<gemm_grid, 256>>>(go, Wp, bp, out);
}

// round 2
// speedup vs baseline: 4.1236x; 4.1236x over previous
#include <cuda_runtime.h>
#include <cstdint>

#define Bsz  4
#define Nseq 2048
#define Cdim 768
#define Hn   12
#define Dh   64
#define Mrows (Bsz * Nseq)   // 8192
#define SCALE_F 0.125f

// Scratch
__device__ float g_q[Mrows * Cdim];   // [B,H,N,D]
__device__ float g_k[Mrows * Cdim];
__device__ float g_v[Mrows * Cdim];
__device__ float g_o[Mrows * Cdim];   // [B,N,C]
__device__ float g_uc[Mrows];

__device__ __forceinline__ uint32_t f2tf(float x) {
    uint32_t u;
    asm("cvt.rna.tf32.f32 %0, %1;" : "=r"(u) : "f"(x));
    return u;
}

__device__ __forceinline__ void mma8(float* d,
    uint32_t a0, uint32_t a1, uint32_t a2, uint32_t a3,
    uint32_t b0, uint32_t b1)
{
    asm("mma.sync.aligned.m16n8k8.row.col.f32.tf32.tf32.f32 "
        "{%0,%1,%2,%3},{%4,%5,%6,%7},{%8,%9},{%0,%1,%2,%3};"
        : "+f"(d[0]), "+f"(d[1]), "+f"(d[2]), "+f"(d[3])
        : "r"(a0), "r"(a1), "r"(a2), "r"(a3), "r"(b0), "r"(b1));
}

// ---------------------------------------------------------------------------
// TF32 GEMM: Y[M,Nc] = A[M,K] @ W^T (W [Nc,K] row-major). 128x128 tile, BK=32.
// 8 warps, each 64(m) x 32(n).
// ---------------------------------------------------------------------------
template<int HEAD_REMAP, int HAS_BIAS>
__global__ __launch_bounds__(256, 2) void gemm_tf32(
    const float* __restrict__ A, const float* __restrict__ W,
    const float* __restrict__ bias, float* __restrict__ Y)
{
    __shared__ uint32_t As[128][36];   // [m][k], bank = (4m+k)%32 -> conflict-free frags
    __shared__ uint32_t Bs[128][36];   // [n][k]

    int t    = threadIdx.x;
    int wid  = t >> 5, lane = t & 31;
    int wm   = (wid >> 2) * 64;        // warp m offset (0/64)
    int wn   = (wid & 3) * 32;         // warp n offset (0..96)
    int r    = lane >> 2, c = lane & 3;
    int m0   = blockIdx.y * 128, n0 = blockIdx.x * 128;

    float acc[4][4][4];
#pragma unroll
    for (int mt = 0; mt < 4; mt++)
#pragma unroll
        for (int nt = 0; nt < 4; nt++)
#pragma unroll
            for (int i = 0; i < 4; i++) acc[mt][nt][i] = 0.0f;

    int lrow = t >> 1;
    int lk   = (t & 1) * 16;
    const float* Ap = A + (size_t)(m0 + lrow) * Cdim + lk;
    const float* Wp = W + (size_t)(n0 + lrow) * Cdim + lk;

    for (int kb = 0; kb < Cdim; kb += 32) {
        float4 av[4], bv[4];
#pragma unroll
        for (int i = 0; i < 4; i++) {
            av[i] = *(const float4*)(Ap + kb + 4 * i);
            bv[i] = *(const float4*)(Wp + kb + 4 * i);
        }
        __syncthreads();
#pragma unroll
        for (int i = 0; i < 4; i++) {
            As[lrow][lk + 4 * i + 0] = f2tf(av[i].x);
            As[lrow][lk + 4 * i + 1] = f2tf(av[i].y);
            As[lrow][lk + 4 * i + 2] = f2tf(av[i].z);
            As[lrow][lk + 4 * i + 3] = f2tf(av[i].w);
            Bs[lrow][lk + 4 * i + 0] = f2tf(bv[i].x);
            Bs[lrow][lk + 4 * i + 1] = f2tf(bv[i].y);
            Bs[lrow][lk + 4 * i + 2] = f2tf(bv[i].z);
            Bs[lrow][lk + 4 * i + 3] = f2tf(bv[i].w);
        }
        __syncthreads();

#pragma unroll
        for (int kk = 0; kk < 32; kk += 8) {
            uint32_t a[4][4], b[4][2];
#pragma unroll
            for (int mt = 0; mt < 4; mt++) {
                a[mt][0] = As[wm + mt * 16 + r    ][kk + c    ];
                a[mt][1] = As[wm + mt * 16 + r + 8][kk + c    ];
                a[mt][2] = As[wm + mt * 16 + r    ][kk + c + 4];
                a[mt][3] = As[wm + mt * 16 + r + 8][kk + c + 4];
            }
#pragma unroll
            for (int nt = 0; nt < 4; nt++) {
                b[nt][0] = Bs[wn + nt * 8 + r][kk + c    ];
                b[nt][1] = Bs[wn + nt * 8 + r][kk + c + 4];
            }
#pragma unroll
            for (int mt = 0; mt < 4; mt++)
#pragma unroll
                for (int nt = 0; nt < 4; nt++)
                    mma8(acc[mt][nt], a[mt][0], a[mt][1], a[mt][2], a[mt][3],
                         b[nt][0], b[nt][1]);
        }
    }

    // Epilogue: c0,c1 at (m, n..n+1); c2,c3 at (m+8, n..n+1)
#pragma unroll
    for (int mt = 0; mt < 4; mt++) {
#pragma unroll
        for (int nt = 0; nt < 4; nt++) {
            int n = n0 + wn + nt * 8 + 2 * c;
            float2 lo = make_float2(acc[mt][nt][0], acc[mt][nt][1]);
            float2 hi = make_float2(acc[mt][nt][2], acc[mt][nt][3]);
            if (HAS_BIAS) {
                float2 bb = *(const float2*)&bias[n];
                lo.x += bb.x; lo.y += bb.y; hi.x += bb.x; hi.y += bb.y;
            }
            int mA = m0 + wm + mt * 16 + r;
            int mB = mA + 8;
            if (HEAD_REMAP) {
                int h = n >> 6, d = n & 63;
                int bA = mA >> 11, nA = mA & (Nseq - 1);
                int bB = mB >> 11, nB = mB & (Nseq - 1);
                *(float2*)&Y[(((size_t)(bA * Hn + h) * Nseq + nA) << 6) + d] = lo;
                *(float2*)&Y[(((size_t)(bB * Hn + h) * Nseq + nB) << 6) + d] = hi;
            } else {
                *(float2*)&Y[(size_t)mA * Cdim + n] = lo;
                *(float2*)&Y[(size_t)mB * Cdim + n] = hi;
            }
        }
    }
}

// ---------------------------------------------------------------------------
// uc[row] = mean over C
// ---------------------------------------------------------------------------
__global__ void uc_kernel(const float* __restrict__ xu, float* __restrict__ uc)
{
    int warp = (blockIdx.x * blockDim.x + threadIdx.x) >> 5;
    int lane = threadIdx.x & 31;
    if (warp >= Mrows) return;
    const float* row = xu + (size_t)warp * Cdim;
    float s = 0.0f;
#pragma unroll
    for (int i = 0; i < Cdim / 32; i++) s += row[lane + i * 32];
#pragma unroll
    for (int m = 16; m; m >>= 1) s += __shfl_xor_sync(0xffffffffu, s, m);
    if (lane == 0) uc[warp] = s * (1.0f / Cdim);
}

// ---------------------------------------------------------------------------
// Fused attention (tf32 mma): BQ=128 per block, 64-key tiles, 8 warps,
// warp = 16 q-rows x 64 keys. Online softmax; P via smem (per-warp rows).
// ---------------------------------------------------------------------------
__global__ __launch_bounds__(256, 2) void attn_tf32(
    const float* __restrict__ Q, const float* __restrict__ K,
    const float* __restrict__ V, const float* __restrict__ UC,
    float* __restrict__ O)
{
    extern __shared__ uint32_t sm[];
    uint32_t* Qs = sm;                    // [128][68]
    uint32_t* Ks = Qs + 128 * 68;         // [64][68]  (keys x d)
    uint32_t* Vs = Ks + 64 * 68;          // [64][68]  (keys x d)
    uint32_t* Ps = Vs + 64 * 68;          // [128][68]

    int t = threadIdx.x, wid = t >> 5, lane = t & 31;
    int r = lane >> 2, c = lane & 3;
    int bh = blockIdx.y;
    int b = bh / Hn, h = bh - b * Hn;
    int q0 = blockIdx.x * 128;

    const float* Qb = Q + ((size_t)bh * Nseq + q0) * Dh;
    const float* Kb = K + (size_t)bh * Nseq * Dh;
    const float* Vb = V + (size_t)bh * Nseq * Dh;

    // Stage Q with SCALE*uc folded in
    {
        int row = t >> 1, d0 = (t & 1) * 32;
        float sc = UC[b * Nseq + q0 + row] * SCALE_F;
#pragma unroll
        for (int i = 0; i < 32; i += 4) {
            float4 v = *(const float4*)(Qb + (size_t)row * Dh + d0 + i);
            Qs[row * 68 + d0 + i + 0] = f2tf(v.x * sc);
            Qs[row * 68 + d0 + i + 1] = f2tf(v.y * sc);
            Qs[row * 68 + d0 + i + 2] = f2tf(v.z * sc);
            Qs[row * 68 + d0 + i + 3] = f2tf(v.w * sc);
        }
    }

    float m_[2] = { -1e30f, -1e30f };
    float l_[2] = { 0.0f, 0.0f };
    float o[8][4];
#pragma unroll
    for (int nt = 0; nt < 8; nt++)
#pragma unroll
        for (int i = 0; i < 4; i++) o[nt][i] = 0.0f;

    int krow = t >> 2, kd0 = (t & 3) * 16;
    int qrow0 = wid * 16 + r;       // this thread's first q row (local)
    int qrow1 = qrow0 + 8;

    for (int kt = 0; kt < Nseq; kt += 64) {
        __syncthreads();   // previous K/V fully consumed (also orders Q stage, iter 0)
#pragma unroll
        for (int i = 0; i < 16; i += 4) {
            float4 kv = *(const float4*)(Kb + (size_t)(kt + krow) * Dh + kd0 + i);
            float4 vv = *(const float4*)(Vb + (size_t)(kt + krow) * Dh + kd0 + i);
            Ks[krow * 68 + kd0 + i + 0] = f2tf(kv.x);
            Ks[krow * 68 + kd0 + i + 1] = f2tf(kv.y);
            Ks[krow * 68 + kd0 + i + 2] = f2tf(kv.z);
            Ks[krow * 68 + kd0 + i + 3] = f2tf(kv.w);
            Vs[krow * 68 + kd0 + i + 0] = f2tf(vv.x);
            Vs[krow * 68 + kd0 + i + 1] = f2tf(vv.y);
            Vs[krow * 68 + kd0 + i + 2] = f2tf(vv.z);
            Vs[krow * 68 + kd0 + i + 3] = f2tf(vv.w);
        }
        __syncthreads();

        // S = Q * K^T  (warp: 16 x 64)
        float s[8][4];
#pragma unroll
        for (int nt = 0; nt < 8; nt++)
#pragma unroll
            for (int i = 0; i < 4; i++) s[nt][i] = 0.0f;

#pragma unroll
        for (int ks = 0; ks < 64; ks += 8) {
            uint32_t a0 = Qs[qrow0 * 68 + ks + c];
            uint32_t a1 = Qs[qrow1 * 68 + ks + c];
            uint32_t a2 = Qs[qrow0 * 68 + ks + c + 4];
            uint32_t a3 = Qs[qrow1 * 68 + ks + c + 4];
#pragma unroll
            for (int nt = 0; nt < 8; nt++) {
                uint32_t b0 = Ks[(nt * 8 + r) * 68 + ks + c];
                uint32_t b1 = Ks[(nt * 8 + r) * 68 + ks + c + 4];
                mma8(s[nt], a0, a1, a2, a3, b0, b1);
            }
        }

        // Online softmax for the 2 rows this thread holds
        float mx0 = -1e30f, mx1 = -1e30f;
#pragma unroll
        for (int nt = 0; nt < 8; nt++) {
            mx0 = fmaxf(mx0, fmaxf(s[nt][0], s[nt][1]));
            mx1 = fmaxf(mx1, fmaxf(s[nt][2], s[nt][3]));
        }
        mx0 = fmaxf(mx0, __shfl_xor_sync(0xffffffffu, mx0, 1));
        mx0 = fmaxf(mx0, __shfl_xor_sync(0xffffffffu, mx0, 2));
        mx1 = fmaxf(mx1, __shfl_xor_sync(0xffffffffu, mx1, 1));
        mx1 = fmaxf(mx1, __shfl_xor_sync(0xffffffffu, mx1, 2));

        float mn0 = fmaxf(m_[0], mx0);
        float mn1 = fmaxf(m_[1], mx1);
        float cor0 = __expf(m_[0] - mn0);
        float cor1 = __expf(m_[1] - mn1);
        m_[0] = mn0; m_[1] = mn1;

        float sum0 = 0.0f, sum1 = 0.0f;
#pragma unroll
        for (int nt = 0; nt < 8; nt++) {
            float p0 = __expf(s[nt][0] - mn0);
            float p1 = __expf(s[nt][1] - mn0);
            float p2 = __expf(s[nt][2] - mn1);
            float p3 = __expf(s[nt][3] - mn1);
            sum0 += p0 + p1;
            sum1 += p2 + p3;
            uint2 lo = make_uint2(f2tf(p0), f2tf(p1));
            uint2 hi = make_uint2(f2tf(p2), f2tf(p3));
            *(uint2*)&Ps[qrow0 * 68 + nt * 8 + 2 * c] = lo;
            *(uint2*)&Ps[qrow1 * 68 + nt * 8 + 2 * c] = hi;
        }
        sum0 += __shfl_xor_sync(0xffffffffu, sum0, 1);
        sum0 += __shfl_xor_sync(0xffffffffu, sum0, 2);
        sum1 += __shfl_xor_sync(0xffffffffu, sum1, 1);
        sum1 += __shfl_xor_sync(0xffffffffu, sum1, 2);
        l_[0] = l_[0] * cor0 + sum0;
        l_[1] = l_[1] * cor1 + sum1;

#pragma unroll
        for (int nt = 0; nt < 8; nt++) {
            o[nt][0] *= cor0; o[nt][1] *= cor0;
            o[nt][2] *= cor1; o[nt][3] *= cor1;
        }

        __syncwarp();   // P rows are per-warp private; order lane writes vs frag reads

        // O += P * V   (A=P rows of this warp, B=V: b0 k=c, n=r)
#pragma unroll
        for (int ks2 = 0; ks2 < 64; ks2 += 8) {
            uint32_t a0 = Ps[qrow0 * 68 + ks2 + c];
            uint32_t a1 = Ps[qrow1 * 68 + ks2 + c];
            uint32_t a2 = Ps[qrow0 * 68 + ks2 + c + 4];
            uint32_t a3 = Ps[qrow1 * 68 + ks2 + c + 4];
#pragma unroll
            for (int nt = 0; nt < 8; nt++) {
                uint32_t b0 = Vs[(ks2 + c    ) * 68 + nt * 8 + r];
                uint32_t b1 = Vs[(ks2 + c + 4) * 68 + nt * 8 + r];
                mma8(o[nt], a0, a1, a2, a3, b0, b1);
            }
        }
        __syncwarp();   // done reading Ps before next iter overwrites
    }

    // Epilogue: normalize and write [B,N,C]
    float inv0 = 1.0f / l_[0];
    float inv1 = 1.0f / l_[1];
    int qg0 = q0 + qrow0;
    int qg1 = q0 + qrow1;
#pragma unroll
    for (int nt = 0; nt < 8; nt++) {
        int d = h * Dh + nt * 8 + 2 * c;
        *(float2*)&O[(size_t)(b * Nseq + qg0) * Cdim + d] =
            make_float2(o[nt][0] * inv0, o[nt][1] * inv0);
        *(float2*)&O[(size_t)(b * Nseq + qg1) * Cdim + d] =
            make_float2(o[nt][2] * inv1, o[nt][3] * inv1);
    }
}

// ---------------------------------------------------------------------------
extern "C" void kernel_launch(void* const* d_in, const int* in_sizes, int n_in,
                              void* d_out, int out_size)
{
    const float* x_q = (const float*)d_in[0];
    const float* x_k = (const float*)d_in[1];
    const float* x_v = (const float*)d_in[2];
    const float* x_u = (const float*)d_in[3];
    const float* Wq  = (const float*)d_in[4];
    const float* Wk  = (const float*)d_in[5];
    const float* Wv  = (const float*)d_in[6];
    const float* Wp  = (const float*)d_in[7];
    const float* bp  = (const float*)d_in[8];
    float* out = (float*)d_out;

    float *gq, *gk, *gv, *go, *guc;
    cudaGetSymbolAddress((void**)&gq,  g_q);
    cudaGetSymbolAddress((void**)&gk,  g_k);
    cudaGetSymbolAddress((void**)&gv,  g_v);
    cudaGetSymbolAddress((void**)&go,  g_o);
    cudaGetSymbolAddress((void**)&guc, g_uc);

    const int ATTN_SMEM = (128 * 68 + 64 * 68 + 64 * 68 + 128 * 68) * 4;  // 104448
    cudaFuncSetAttribute(attn_tf32, cudaFuncAttributeMaxDynamicSharedMemorySize, ATTN_SMEM);

    dim3 gemm_grid(Cdim / 128, Mrows / 128);   // (6, 64)
    gemm_tf32<1, 0><<<gemm_grid, 256>>>(x_q, Wq, nullptr, gq);
    gemm_tf32<1, 0><<<gemm_grid, 256>>>(x_k, Wk, nullptr, gk);
    gemm_tf32<1, 0><<<gemm_grid, 256>>>(x_v, Wv, nullptr, gv);

    uc_kernel<<<Mrows / 8, 256>>>(x_u, guc);

    dim3 attn_grid(Nseq / 128, Bsz * Hn);      // (16, 48)
    attn_tf32<<<attn_grid, 256, ATTN_SMEM>>>(gq, gk, gv, guc, go);

    gemm_tf32<0, 1><<<gemm_grid, 256>>>(go, Wp, bp, out);
}